// round 4
// baseline (speedup 1.0000x reference)
#include <cuda_runtime.h>
#include <cstdint>

// Problem constants
#define B_   8
#define N_   2048
#define FIN  256
#define FOUT 128
#define ROWS_TOTAL (B_ * N_)   // 16384

// -------- static device scratch (no allocations allowed) --------
__device__ float  d_Wh[(size_t)ROWS_TOTAL * FOUT];   // 8 MB
__device__ float  d_si[ROWS_TOTAL];
__device__ float  d_sj[ROWS_TOTAL];
__device__ float2 d_E12[ROWS_TOTAL];                 // (exp(si+smax-m), exp(0.01*(si+smax)-m))
__device__ float2 d_F12[ROWS_TOTAL];                 // (exp(sj-smax),   exp(0.01*(sj-smax)))
__device__ float  d_smax[B_];

// -------- packed f32x2 helpers (Blackwell FFMA2: PTX-only) --------
__device__ __forceinline__ unsigned long long ffma2(unsigned long long a,
                                                    unsigned long long b,
                                                    unsigned long long c) {
    unsigned long long d;
    asm("fma.rn.f32x2 %0, %1, %2, %3;" : "=l"(d) : "l"(a), "l"(b), "l"(c));
    return d;
}
__device__ __forceinline__ unsigned long long pack2(float lo, float hi) {
    unsigned long long d;
    asm("mov.b64 %0, {%1, %2};" : "=l"(d) : "f"(lo), "f"(hi));
    return d;
}
union F2U { unsigned long long u; float2 f; };

// ============================================================================
// Kernel A: Wh = h @ W_fc      [16384 x 256] @ [256 x 128]
// 256 threads, 32 rows/block; thread = (1 row) x (16 cols); FFMA2 mainloop.
// ============================================================================
__global__ __launch_bounds__(256) void wh_kernel(const float* __restrict__ h,
                                                 const float* __restrict__ W) {
    __shared__ float sh[32][65];  // 32 rows x 64-k tile, padded
    const int t      = threadIdx.x;
    const int colgrp = t & 7;          // 8 col groups of 16
    const int rsub   = t >> 3;         // 0..31
    const int row0   = blockIdx.x * 32;
    const int c0     = colgrp * 16;

    unsigned long long acc[8];
    #pragma unroll
    for (int i = 0; i < 8; i++) acc[i] = 0ull;  // bits of (0.f,0.f)

    for (int k0 = 0; k0 < FIN; k0 += 64) {
        __syncthreads();
        // stage h[row0..row0+32)[k0..k0+64): 32 rows x 16 float4
        for (int i = t; i < 32 * 16; i += 256) {
            int r  = i >> 4;
            int kq = i & 15;
            float4 v = *(const float4*)&h[(size_t)(row0 + r) * FIN + k0 + kq * 4];
            sh[r][kq * 4 + 0] = v.x; sh[r][kq * 4 + 1] = v.y;
            sh[r][kq * 4 + 2] = v.z; sh[r][kq * 4 + 3] = v.w;
        }
        __syncthreads();

        #pragma unroll 8
        for (int kk = 0; kk < 64; kk++) {
            const int k = k0 + kk;
            const float hv = sh[rsub][kk];
            const unsigned long long hp = pack2(hv, hv);
            const ulonglong2* wp = (const ulonglong2*)&W[(size_t)k * FOUT + c0];
            ulonglong2 w01 = wp[0];
            ulonglong2 w23 = wp[1];
            ulonglong2 w45 = wp[2];
            ulonglong2 w67 = wp[3];
            acc[0] = ffma2(w01.x, hp, acc[0]);
            acc[1] = ffma2(w01.y, hp, acc[1]);
            acc[2] = ffma2(w23.x, hp, acc[2]);
            acc[3] = ffma2(w23.y, hp, acc[3]);
            acc[4] = ffma2(w45.x, hp, acc[4]);
            acc[5] = ffma2(w45.y, hp, acc[5]);
            acc[6] = ffma2(w67.x, hp, acc[6]);
            acc[7] = ffma2(w67.y, hp, acc[7]);
        }
    }

    float* outp = &d_Wh[(size_t)(row0 + rsub) * FOUT + c0];
    #pragma unroll
    for (int q = 0; q < 4; q++) {
        F2U a0, a1; a0.u = acc[2 * q]; a1.u = acc[2 * q + 1];
        ((float4*)outp)[q] = make_float4(a0.f.x, a0.f.y, a1.f.x, a1.f.y);
    }
}

// ============================================================================
// Kernel B1: s_i = Wh @ a_i, s_j = Wh @ a_j   (one warp per row)
// ============================================================================
__global__ __launch_bounds__(256) void s_kernel(const float* __restrict__ a_i,
                                                const float* __restrict__ a_j) {
    const int warp = threadIdx.x >> 5;
    const int lane = threadIdx.x & 31;
    const int row  = blockIdx.x * 8 + warp;
    if (row >= ROWS_TOTAL) return;

    float4 v  = ((const float4*)&d_Wh[(size_t)row * FOUT])[lane];
    float4 ai = ((const float4*)a_i)[lane];
    float4 aj = ((const float4*)a_j)[lane];
    float si = v.x * ai.x + v.y * ai.y + v.z * ai.z + v.w * ai.w;
    float sj = v.x * aj.x + v.y * aj.y + v.z * aj.z + v.w * aj.w;
    #pragma unroll
    for (int m = 16; m > 0; m >>= 1) {
        si += __shfl_xor_sync(0xffffffffu, si, m);
        sj += __shfl_xor_sync(0xffffffffu, sj, m);
    }
    if (lane == 0) { d_si[row] = si; d_sj[row] = sj; }
}

// ============================================================================
// Kernel B2: per-batch max over s_j
// ============================================================================
__global__ __launch_bounds__(256) void smax_kernel() {
    __shared__ float red[256];
    const int b = blockIdx.x;
    const int t = threadIdx.x;
    float m = -3.0e38f;
    for (int j = t; j < N_; j += 256) m = fmaxf(m, d_sj[b * N_ + j]);
    red[t] = m;
    __syncthreads();
    for (int s = 128; s > 0; s >>= 1) {
        if (t < s) red[t] = fmaxf(red[t], red[t + s]);
        __syncthreads();
    }
    if (t == 0) d_smax[b] = red[0];
}

// ============================================================================
// Kernel B3: exp tables.
// p_ij = exp(lrelu(s_i+s_j) - m_i),  m_i = lrelu(s_i + smax_b)  (monotone lrelu)
//      = max( E1_i*F1_j , E2_i*F2_j )   since lrelu(t)=max(t,0.01t) and exp monotone.
// ============================================================================
__global__ __launch_bounds__(256) void tables_kernel() {
    const int idx = blockIdx.x * 256 + threadIdx.x;
    if (idx >= ROWS_TOTAL) return;
    const int b = idx >> 11;           // /2048
    const float sm = d_smax[b];
    const float si = d_si[idx];
    const float sj = d_sj[idx];

    const float tt = si + sm;
    const float m  = fmaxf(tt, 0.01f * tt);     // = lrelu(si + smax) = row max of scores
    d_E12[idx] = make_float2(__expf(tt - m) , __expf(0.01f * tt - m));
    const float u = sj - sm;                    // <= 0
    d_F12[idx] = make_float2(__expf(u), __expf(0.01f * u));
}

// ============================================================================
// Kernel C: fused softmax-weight generation + h' = alpha @ Wh
// Grid (N/32, B); 256 threads; thread = (1 row) x (16 cols), loops all 2048 j.
// Weight p needs NO exp in the inner loop: p = max(e1*f1[j], e2*f2[j]).
// ============================================================================
__global__ __launch_bounds__(256) void attn_kernel(float* __restrict__ out) {
    __shared__ float2 fsh[N_];   // 16 KB: F12 table for this batch
    const int t      = threadIdx.x;
    const int colgrp = t & 7;
    const int rsub   = t >> 3;
    const int b      = blockIdx.y;
    const int row    = blockIdx.x * 32 + rsub;  // row within batch
    const int c0     = colgrp * 16;

    // stage F12[b,:] into smem (1024 float4)
    {
        const float4* src = (const float4*)&d_F12[b * N_];
        float4* dst = (float4*)fsh;
        for (int i = t; i < N_ / 2; i += 256) dst[i] = src[i];
    }
    __syncthreads();

    const float2 e = d_E12[b * N_ + row];
    const float e1 = e.x, e2 = e.y;

    unsigned long long acc[8];
    #pragma unroll
    for (int i = 0; i < 8; i++) acc[i] = 0ull;
    float Z = 0.0f;

    const ulonglong2* whbase =
        (const ulonglong2*)&d_Wh[(size_t)b * N_ * FOUT + c0];
    // stride per j in ulonglong2 units: 128 floats = 512 B = 32 ulonglong2

    #pragma unroll 4
    for (int j = 0; j < N_; j++) {
        const float2 f = fsh[j];
        const float p = fmaxf(e1 * f.x, e2 * f.y);
        Z += p;
        const unsigned long long pp = pack2(p, p);
        const ulonglong2* wp = whbase + (size_t)j * 32;
        ulonglong2 w01 = wp[0];
        ulonglong2 w23 = wp[1];
        ulonglong2 w45 = wp[2];
        ulonglong2 w67 = wp[3];
        acc[0] = ffma2(w01.x, pp, acc[0]);
        acc[1] = ffma2(w01.y, pp, acc[1]);
        acc[2] = ffma2(w23.x, pp, acc[2]);
        acc[3] = ffma2(w23.y, pp, acc[3]);
        acc[4] = ffma2(w45.x, pp, acc[4]);
        acc[5] = ffma2(w45.y, pp, acc[5]);
        acc[6] = ffma2(w67.x, pp, acc[6]);
        acc[7] = ffma2(w67.y, pp, acc[7]);
    }

    const float rZ = 1.0f / Z;
    float* outp = &out[((size_t)b * N_ + row) * FOUT + c0];
    #pragma unroll
    for (int q = 0; q < 4; q++) {
        F2U a0, a1; a0.u = acc[2 * q]; a1.u = acc[2 * q + 1];
        ((float4*)outp)[q] =
            make_float4(a0.f.x * rZ, a0.f.y * rZ, a1.f.x * rZ, a1.f.y * rZ);
    }
}

// ============================================================================
// launch
// ============================================================================
extern "C" void kernel_launch(void* const* d_in, const int* in_sizes, int n_in,
                              void* d_out, int out_size) {
    const float* h    = (const float*)d_in[0];  // [8,2048,256]
    const float* W_fc = (const float*)d_in[1];  // [256,128]
    const float* a_i  = (const float*)d_in[2];  // [128]
    const float* a_j  = (const float*)d_in[3];  // [128]
    float* out = (float*)d_out;                 // [8,2048,128]

    wh_kernel<<<ROWS_TOTAL / 32, 256>>>(h, W_fc);
    s_kernel<<<ROWS_TOTAL / 8, 256>>>(a_i, a_j);
    smax_kernel<<<B_, 256>>>();
    tables_kernel<<<ROWS_TOTAL / 256, 256>>>();
    dim3 grid(N_ / 32, B_);
    attn_kernel<<<grid, 256>>>(out);
}

// round 5
// speedup vs baseline: 7.7959x; 7.7959x over previous
#include <cuda_runtime.h>
#include <cstdint>

// Problem constants
#define B_   8
#define N_   2048
#define FIN  256
#define FOUT 128
#define ROWS_TOTAL (B_ * N_)   // 16384

typedef unsigned long long ull;

// -------- static device scratch (no allocations allowed) --------
__device__ float  d_Wh[(size_t)ROWS_TOTAL * FOUT];   // 8 MB
__device__ float  d_si[ROWS_TOTAL];
__device__ float  d_sj[ROWS_TOTAL];
__device__ float2 d_E12[ROWS_TOTAL];                 // (exp(si+smax-m), exp(0.01*(si+smax)-m))
__device__ float2 d_F12[ROWS_TOTAL];                 // (exp(sj-smax),   exp(0.01*(sj-smax)))
__device__ float  d_smax[B_];

// -------- packed f32x2 helpers (Blackwell FFMA2: PTX-only) --------
__device__ __forceinline__ ull ffma2(ull a, ull b, ull c) {
    ull d;
    asm("fma.rn.f32x2 %0, %1, %2, %3;" : "=l"(d) : "l"(a), "l"(b), "l"(c));
    return d;
}
__device__ __forceinline__ ull pack2(float lo, float hi) {
    ull d;
    asm("mov.b64 %0, {%1, %2};" : "=l"(d) : "f"(lo), "f"(hi));
    return d;
}
__device__ __forceinline__ float2 unpack2(ull v) {
    float2 r;
    asm("mov.b64 {%0, %1}, %2;" : "=f"(r.x), "=f"(r.y) : "l"(v));
    return r;
}

// ============================================================================
// Kernel A: Wh = h @ W_fc    [16384 x 256] @ [256 x 128]
// Block: 64 rows x 128 cols, K-tile 32, 256 threads, thread tile 4 rows x 8 cols.
// a-side: h values duplicated into smem pairs (transposed); b-side: W row-major
// tile, natural col-pairs via LDS.128. 16 FFMA2 per thread per k.
// ============================================================================
__global__ __launch_bounds__(256) void wh_kernel(const float* __restrict__ h,
                                                 const float* __restrict__ W) {
    __shared__ __align__(16) ull   hdup[32][67];   // [k][row] dup pairs (padded)
    __shared__ __align__(16) float wsm[32][128];   // [k][col]
    const int t    = threadIdx.x;
    const int rt   = t >> 4;        // 0..15 -> rows 4rt..4rt+3
    const int ct   = t & 15;        // cols 4ct..4ct+3 and 64+4ct..64+4ct+3
    const int row0 = blockIdx.x * 64;

    ull acc[4][4];
    #pragma unroll
    for (int r = 0; r < 4; r++)
        #pragma unroll
        for (int c = 0; c < 4; c++) acc[r][c] = 0ull;

    for (int k0 = 0; k0 < FIN; k0 += 32) {
        __syncthreads();
        // stage hdup: 64 rows x 32 k, transposed + duplicated (2 float4/thread)
        #pragma unroll
        for (int m = 0; m < 2; m++) {
            int idx = t + m * 256;           // float4 index 0..511
            int r   = idx >> 3;              // 8 float4 per row
            int kq  = idx & 7;
            float4 v = *(const float4*)&h[(size_t)(row0 + r) * FIN + k0 + kq * 4];
            hdup[kq * 4 + 0][r] = pack2(v.x, v.x);
            hdup[kq * 4 + 1][r] = pack2(v.y, v.y);
            hdup[kq * 4 + 2][r] = pack2(v.z, v.z);
            hdup[kq * 4 + 3][r] = pack2(v.w, v.w);
        }
        // stage wsm: 32 k x 128 cols (4 float4/thread, contiguous STS.128)
        #pragma unroll
        for (int m = 0; m < 4; m++) {
            int idx = t + m * 256;           // float4 index 0..1023
            int k   = idx >> 5;              // 32 float4 per k-row
            int cq  = idx & 31;
            *(float4*)&wsm[k][cq * 4] =
                *(const float4*)&W[(size_t)(k0 + k) * FOUT + cq * 4];
        }
        __syncthreads();

        #pragma unroll 8
        for (int kk = 0; kk < 32; kk++) {
            ull a0 = hdup[kk][4 * rt + 0];
            ull a1 = hdup[kk][4 * rt + 1];
            ull a2 = hdup[kk][4 * rt + 2];
            ull a3 = hdup[kk][4 * rt + 3];
            ulonglong2 b0 = *(const ulonglong2*)&wsm[kk][4 * ct];
            ulonglong2 b1 = *(const ulonglong2*)&wsm[kk][64 + 4 * ct];
            acc[0][0] = ffma2(a0, b0.x, acc[0][0]);
            acc[0][1] = ffma2(a0, b0.y, acc[0][1]);
            acc[0][2] = ffma2(a0, b1.x, acc[0][2]);
            acc[0][3] = ffma2(a0, b1.y, acc[0][3]);
            acc[1][0] = ffma2(a1, b0.x, acc[1][0]);
            acc[1][1] = ffma2(a1, b0.y, acc[1][1]);
            acc[1][2] = ffma2(a1, b1.x, acc[1][2]);
            acc[1][3] = ffma2(a1, b1.y, acc[1][3]);
            acc[2][0] = ffma2(a2, b0.x, acc[2][0]);
            acc[2][1] = ffma2(a2, b0.y, acc[2][1]);
            acc[2][2] = ffma2(a2, b1.x, acc[2][2]);
            acc[2][3] = ffma2(a2, b1.y, acc[2][3]);
            acc[3][0] = ffma2(a3, b0.x, acc[3][0]);
            acc[3][1] = ffma2(a3, b0.y, acc[3][1]);
            acc[3][2] = ffma2(a3, b1.x, acc[3][2]);
            acc[3][3] = ffma2(a3, b1.y, acc[3][3]);
        }
    }

    #pragma unroll
    for (int r = 0; r < 4; r++) {
        float2 c0 = unpack2(acc[r][0]);
        float2 c1 = unpack2(acc[r][1]);
        float2 c2 = unpack2(acc[r][2]);
        float2 c3 = unpack2(acc[r][3]);
        float* o = &d_Wh[(size_t)(row0 + 4 * rt + r) * FOUT];
        *(float4*)&o[4 * ct]      = make_float4(c0.x, c0.y, c1.x, c1.y);
        *(float4*)&o[64 + 4 * ct] = make_float4(c2.x, c2.y, c3.x, c3.y);
    }
}

// ============================================================================
// Kernel B1: s_i = Wh @ a_i, s_j = Wh @ a_j   (one warp per row)
// ============================================================================
__global__ __launch_bounds__(256) void s_kernel(const float* __restrict__ a_i,
                                                const float* __restrict__ a_j) {
    const int warp = threadIdx.x >> 5;
    const int lane = threadIdx.x & 31;
    const int row  = blockIdx.x * 8 + warp;
    if (row >= ROWS_TOTAL) return;

    float4 v  = ((const float4*)&d_Wh[(size_t)row * FOUT])[lane];
    float4 ai = ((const float4*)a_i)[lane];
    float4 aj = ((const float4*)a_j)[lane];
    float si = v.x * ai.x + v.y * ai.y + v.z * ai.z + v.w * ai.w;
    float sj = v.x * aj.x + v.y * aj.y + v.z * aj.z + v.w * aj.w;
    #pragma unroll
    for (int m = 16; m > 0; m >>= 1) {
        si += __shfl_xor_sync(0xffffffffu, si, m);
        sj += __shfl_xor_sync(0xffffffffu, sj, m);
    }
    if (lane == 0) { d_si[row] = si; d_sj[row] = sj; }
}

// ============================================================================
// Kernel B2: per-batch max over s_j
// ============================================================================
__global__ __launch_bounds__(256) void smax_kernel() {
    __shared__ float red[256];
    const int b = blockIdx.x;
    const int t = threadIdx.x;
    float m = -3.0e38f;
    for (int j = t; j < N_; j += 256) m = fmaxf(m, d_sj[b * N_ + j]);
    red[t] = m;
    __syncthreads();
    for (int s = 128; s > 0; s >>= 1) {
        if (t < s) red[t] = fmaxf(red[t], red[t + s]);
        __syncthreads();
    }
    if (t == 0) d_smax[b] = red[0];
}

// ============================================================================
// Kernel B3: exp tables.
// p_ij = exp(lrelu(s_i+s_j) - m_i),  m_i = lrelu(s_i + smax_b)  (monotone lrelu)
//      = max( E1_i*F1_j , E2_i*F2_j )
// ============================================================================
__global__ __launch_bounds__(256) void tables_kernel() {
    const int idx = blockIdx.x * 256 + threadIdx.x;
    if (idx >= ROWS_TOTAL) return;
    const int b = idx >> 11;
    const float sm = d_smax[b];
    const float si = d_si[idx];
    const float sj = d_sj[idx];

    const float tt = si + sm;
    const float m  = fmaxf(tt, 0.01f * tt);
    d_E12[idx] = make_float2(__expf(tt - m), __expf(0.01f * tt - m));
    const float u = sj - sm;
    d_F12[idx] = make_float2(__expf(u), __expf(0.01f * u));
}

// ============================================================================
// Kernel C: fused  h' = softmax_row( max(E1_i F1_j, E2_i F2_j) ) @ Wh
// Block: 64 rows x 128 cols, K(=j)-tile 32, 256 threads, thread tile 4x8.
// Per K-tile: stage Wh tile (once per block, not per thread-row!), generate
// alpha-weight dup-pairs into smem, then 16 FFMA2 per thread per j.
// Z accumulated by the generating threads; normalize in the epilogue.
// ============================================================================
__global__ __launch_bounds__(256) void attn_kernel(float* __restrict__ out) {
    __shared__ __align__(16) ull   pdup[32][64];   // [j][row] dup pairs (16 KB)
    __shared__ __align__(16) float wsm[32][128];   // [j][col]  Wh tile  (16 KB)
    __shared__ float zsm[4][64];
    __shared__ float rzsm[64];

    const int t    = threadIdx.x;
    const int rt   = t >> 4;        // 0..15 -> rows 4rt..4rt+3
    const int ct   = t & 15;        // cols 4ct..+3 and 64+4ct..+3
    const int row0 = blockIdx.x * 64;       // global row (64 | 2048 -> no batch split)
    const int b    = row0 >> 11;
    const int gi   = t & 63;        // p-gen: row within block
    const int jg   = t >> 6;        // p-gen: j-subgroup 0..3

    const float2 e  = d_E12[row0 + gi];
    const float  e1 = e.x, e2 = e.y;
    float zacc = 0.0f;

    ull acc[4][4];
    #pragma unroll
    for (int r = 0; r < 4; r++)
        #pragma unroll
        for (int c = 0; c < 4; c++) acc[r][c] = 0ull;

    const float* whb = &d_Wh[(size_t)b * N_ * FOUT];

    for (int j0 = 0; j0 < N_; j0 += 32) {
        __syncthreads();
        // stage Wh tile: 32 j x 128 cols (4 float4/thread, contiguous)
        #pragma unroll
        for (int m = 0; m < 4; m++) {
            int idx = t + m * 256;
            int j   = idx >> 5;
            int cq  = idx & 31;
            *(float4*)&wsm[j][cq * 4] =
                *(const float4*)&whb[(size_t)(j0 + j) * FOUT + cq * 4];
        }
        // generate alpha weights (dup pairs) + accumulate Z partials
        #pragma unroll
        for (int jj = 0; jj < 8; jj++) {
            int j = jg * 8 + jj;
            float2 f = d_F12[b * N_ + j0 + j];
            float p = fmaxf(e1 * f.x, e2 * f.y);
            zacc += p;
            pdup[j][gi] = pack2(p, p);
        }
        __syncthreads();

        #pragma unroll 8
        for (int kk = 0; kk < 32; kk++) {
            ulonglong2 a01 = *(const ulonglong2*)&pdup[kk][4 * rt];
            ulonglong2 a23 = *(const ulonglong2*)&pdup[kk][4 * rt + 2];
            ulonglong2 b0  = *(const ulonglong2*)&wsm[kk][4 * ct];
            ulonglong2 b1  = *(const ulonglong2*)&wsm[kk][64 + 4 * ct];
            acc[0][0] = ffma2(a01.x, b0.x, acc[0][0]);
            acc[0][1] = ffma2(a01.x, b0.y, acc[0][1]);
            acc[0][2] = ffma2(a01.x, b1.x, acc[0][2]);
            acc[0][3] = ffma2(a01.x, b1.y, acc[0][3]);
            acc[1][0] = ffma2(a01.y, b0.x, acc[1][0]);
            acc[1][1] = ffma2(a01.y, b0.y, acc[1][1]);
            acc[1][2] = ffma2(a01.y, b1.x, acc[1][2]);
            acc[1][3] = ffma2(a01.y, b1.y, acc[1][3]);
            acc[2][0] = ffma2(a23.x, b0.x, acc[2][0]);
            acc[2][1] = ffma2(a23.x, b0.y, acc[2][1]);
            acc[2][2] = ffma2(a23.x, b1.x, acc[2][2]);
            acc[2][3] = ffma2(a23.x, b1.y, acc[2][3]);
            acc[3][0] = ffma2(a23.y, b0.x, acc[3][0]);
            acc[3][1] = ffma2(a23.y, b0.y, acc[3][1]);
            acc[3][2] = ffma2(a23.y, b1.x, acc[3][2]);
            acc[3][3] = ffma2(a23.y, b1.y, acc[3][3]);
        }
    }

    // Z reduction: 4 partials per row
    zsm[jg][gi] = zacc;
    __syncthreads();
    if (t < 64) {
        float Z = zsm[0][t] + zsm[1][t] + zsm[2][t] + zsm[3][t];
        rzsm[t] = 1.0f / Z;
    }
    __syncthreads();

    #pragma unroll
    for (int r = 0; r < 4; r++) {
        const float rz = rzsm[4 * rt + r];
        float2 c0 = unpack2(acc[r][0]);
        float2 c1 = unpack2(acc[r][1]);
        float2 c2 = unpack2(acc[r][2]);
        float2 c3 = unpack2(acc[r][3]);
        float* o = &out[(size_t)(row0 + 4 * rt + r) * FOUT];
        *(float4*)&o[4 * ct] =
            make_float4(c0.x * rz, c0.y * rz, c1.x * rz, c1.y * rz);
        *(float4*)&o[64 + 4 * ct] =
            make_float4(c2.x * rz, c2.y * rz, c3.x * rz, c3.y * rz);
    }
}

// ============================================================================
// launch
// ============================================================================
extern "C" void kernel_launch(void* const* d_in, const int* in_sizes, int n_in,
                              void* d_out, int out_size) {
    const float* h    = (const float*)d_in[0];  // [8,2048,256]
    const float* W_fc = (const float*)d_in[1];  // [256,128]
    const float* a_i  = (const float*)d_in[2];  // [128]
    const float* a_j  = (const float*)d_in[3];  // [128]
    float* out = (float*)d_out;                 // [8,2048,128]

    wh_kernel<<<ROWS_TOTAL / 64, 256>>>(h, W_fc);
    s_kernel<<<ROWS_TOTAL / 8, 256>>>(a_i, a_j);
    smax_kernel<<<B_, 256>>>();
    tables_kernel<<<ROWS_TOTAL / 256, 256>>>();
    attn_kernel<<<ROWS_TOTAL / 64, 256>>>(out);
}

// round 9
// speedup vs baseline: 18.3043x; 2.3480x over previous
#include <cuda_runtime.h>
#include <cuda_bf16.h>
#include <cstdint>

#define B_   8
#define N_   2048
#define FIN  256
#define FOUT 128
#define ROWS_TOTAL (B_ * N_)   // 16384

typedef unsigned long long ull;

// -------- static device scratch --------
__device__ __align__(16) float d_Wh[(size_t)ROWS_TOTAL * FOUT];             // 8 MB fp32 [b*N+j][o]
__device__ __align__(16) __nv_bfloat16 d_Whbf_hi[(size_t)ROWS_TOTAL * FOUT]; // 4 MB same layout
__device__ __align__(16) __nv_bfloat16 d_Whbf_lo[(size_t)ROWS_TOTAL * FOUT]; // 4 MB
__device__ float  d_si[ROWS_TOTAL];
__device__ float  d_sj[ROWS_TOTAL];
__device__ __align__(16) float2 d_E12[ROWS_TOTAL];
__device__ __align__(16) float2 d_F12[ROWS_TOTAL];
__device__ float  d_smax[B_];

// -------- packed f32x2 helpers --------
__device__ __forceinline__ ull ffma2(ull a, ull b, ull c) {
    ull d;
    asm("fma.rn.f32x2 %0, %1, %2, %3;" : "=l"(d) : "l"(a), "l"(b), "l"(c));
    return d;
}
__device__ __forceinline__ ull pack2(float lo, float hi) {
    ull d;
    asm("mov.b64 %0, {%1, %2};" : "=l"(d) : "f"(lo), "f"(hi));
    return d;
}
__device__ __forceinline__ float2 unpack2(ull v) {
    float2 r;
    asm("mov.b64 {%0, %1}, %2;" : "=f"(r.x), "=f"(r.y) : "l"(v));
    return r;
}

// bf16 pack/split helpers. CVTPK(res,a,b): res = bf16x2 {lo=a, hi=b} (memory order a,b)
#define CVTPK(res, a, b) \
    asm("cvt.rn.satfinite.bf16x2.f32 %0, %1, %2;" : "=r"(res) : "f"(b), "f"(a))
__device__ __forceinline__ float loF(uint32_t h) { return __uint_as_float(h << 16); }
__device__ __forceinline__ float hiF(uint32_t h) { return __uint_as_float(h & 0xffff0000u); }

__device__ __forceinline__ uint32_t smem_to_u32(const void* p) {
    uint32_t a;
    asm("{ .reg .u64 t; cvta.to.shared.u64 t, %1; cvt.u32.u64 %0, t; }" : "=r"(a) : "l"(p));
    return a;
}
__device__ __forceinline__ void cp16(uint32_t s, const void* g) {
    asm volatile("cp.async.cg.shared.global [%0], [%1], 16;" :: "r"(s), "l"(g) : "memory");
}
#define CP_COMMIT() asm volatile("cp.async.commit_group;" ::: "memory")
#define CP_WAIT0()  asm volatile("cp.async.wait_group 0;" ::: "memory")

__device__ __forceinline__ void ldsm4(uint32_t& r0, uint32_t& r1, uint32_t& r2,
                                      uint32_t& r3, uint32_t a) {
    asm volatile("ldmatrix.sync.aligned.m8n8.x4.shared.b16 {%0,%1,%2,%3}, [%4];"
                 : "=r"(r0), "=r"(r1), "=r"(r2), "=r"(r3) : "r"(a));
}
__device__ __forceinline__ void ldsm4t(uint32_t& r0, uint32_t& r1, uint32_t& r2,
                                       uint32_t& r3, uint32_t a) {
    asm volatile("ldmatrix.sync.aligned.m8n8.x4.trans.shared.b16 {%0,%1,%2,%3}, [%4];"
                 : "=r"(r0), "=r"(r1), "=r"(r2), "=r"(r3) : "r"(a));
}
__device__ __forceinline__ void mma16816(float* c, uint32_t a0, uint32_t a1,
                                         uint32_t a2, uint32_t a3,
                                         uint32_t b0, uint32_t b1) {
    asm volatile("mma.sync.aligned.m16n8k16.row.col.f32.bf16.bf16.f32 "
                 "{%0,%1,%2,%3}, {%4,%5,%6,%7}, {%8,%9}, {%0,%1,%2,%3};"
                 : "+f"(c[0]), "+f"(c[1]), "+f"(c[2]), "+f"(c[3])
                 : "r"(a0), "r"(a1), "r"(a2), "r"(a3), "r"(b0), "r"(b1));
}

// ============================================================================
// Kernel A: Wh = h @ W_fc  (FFMA2, 64 rows x 128 cols / block) + bf16 hi/lo split
// ============================================================================
__global__ __launch_bounds__(256) void wh_kernel(const float* __restrict__ h,
                                                 const float* __restrict__ W) {
    __shared__ __align__(16) ull   hdup[32][67];
    __shared__ __align__(16) float wsm[32][128];
    const int t    = threadIdx.x;
    const int rt   = t >> 4;
    const int ct   = t & 15;
    const int row0 = blockIdx.x * 64;

    ull acc[4][4];
    #pragma unroll
    for (int r = 0; r < 4; r++)
        #pragma unroll
        for (int c = 0; c < 4; c++) acc[r][c] = 0ull;

    for (int k0 = 0; k0 < FIN; k0 += 32) {
        __syncthreads();
        #pragma unroll
        for (int m = 0; m < 2; m++) {
            int idx = t + m * 256;
            int r   = idx >> 3;
            int kq  = idx & 7;
            float4 v = *(const float4*)&h[(size_t)(row0 + r) * FIN + k0 + kq * 4];
            hdup[kq * 4 + 0][r] = pack2(v.x, v.x);
            hdup[kq * 4 + 1][r] = pack2(v.y, v.y);
            hdup[kq * 4 + 2][r] = pack2(v.z, v.z);
            hdup[kq * 4 + 3][r] = pack2(v.w, v.w);
        }
        #pragma unroll
        for (int m = 0; m < 4; m++) {
            int idx = t + m * 256;
            int k   = idx >> 5;
            int cq  = idx & 31;
            *(float4*)&wsm[k][cq * 4] =
                *(const float4*)&W[(size_t)(k0 + k) * FOUT + cq * 4];
        }
        __syncthreads();

        #pragma unroll 8
        for (int kk = 0; kk < 32; kk++) {
            ull a0 = hdup[kk][4 * rt + 0];
            ull a1 = hdup[kk][4 * rt + 1];
            ull a2 = hdup[kk][4 * rt + 2];
            ull a3 = hdup[kk][4 * rt + 3];
            ulonglong2 b0 = *(const ulonglong2*)&wsm[kk][4 * ct];
            ulonglong2 b1 = *(const ulonglong2*)&wsm[kk][64 + 4 * ct];
            acc[0][0] = ffma2(a0, b0.x, acc[0][0]);
            acc[0][1] = ffma2(a0, b0.y, acc[0][1]);
            acc[0][2] = ffma2(a0, b1.x, acc[0][2]);
            acc[0][3] = ffma2(a0, b1.y, acc[0][3]);
            acc[1][0] = ffma2(a1, b0.x, acc[1][0]);
            acc[1][1] = ffma2(a1, b0.y, acc[1][1]);
            acc[1][2] = ffma2(a1, b1.x, acc[1][2]);
            acc[1][3] = ffma2(a1, b1.y, acc[1][3]);
            acc[2][0] = ffma2(a2, b0.x, acc[2][0]);
            acc[2][1] = ffma2(a2, b0.y, acc[2][1]);
            acc[2][2] = ffma2(a2, b1.x, acc[2][2]);
            acc[2][3] = ffma2(a2, b1.y, acc[2][3]);
            acc[3][0] = ffma2(a3, b0.x, acc[3][0]);
            acc[3][1] = ffma2(a3, b0.y, acc[3][1]);
            acc[3][2] = ffma2(a3, b1.x, acc[3][2]);
            acc[3][3] = ffma2(a3, b1.y, acc[3][3]);
        }
    }

    #pragma unroll
    for (int r = 0; r < 4; r++) {
        float2 c0 = unpack2(acc[r][0]);
        float2 c1 = unpack2(acc[r][1]);
        float2 c2 = unpack2(acc[r][2]);
        float2 c3 = unpack2(acc[r][3]);
        const size_t row = (size_t)(row0 + 4 * rt + r);
        float* o = &d_Wh[row * FOUT];
        *(float4*)&o[4 * ct]      = make_float4(c0.x, c0.y, c1.x, c1.y);
        *(float4*)&o[64 + 4 * ct] = make_float4(c2.x, c2.y, c3.x, c3.y);

        // bf16 hi/lo split, same [row][col] layout
        uint32_t H0, H1, H2, H3;
        CVTPK(H0, c0.x, c0.y); CVTPK(H1, c1.x, c1.y);
        CVTPK(H2, c2.x, c2.y); CVTPK(H3, c3.x, c3.y);
        float l0x = c0.x - loF(H0), l0y = c0.y - hiF(H0);
        float l1x = c1.x - loF(H1), l1y = c1.y - hiF(H1);
        float l2x = c2.x - loF(H2), l2y = c2.y - hiF(H2);
        float l3x = c3.x - loF(H3), l3y = c3.y - hiF(H3);
        uint32_t L0, L1, L2, L3;
        CVTPK(L0, l0x, l0y); CVTPK(L1, l1x, l1y);
        CVTPK(L2, l2x, l2y); CVTPK(L3, l3x, l3y);
        *(uint2*)&d_Whbf_hi[row * FOUT + 4 * ct]      = make_uint2(H0, H1);
        *(uint2*)&d_Whbf_hi[row * FOUT + 64 + 4 * ct] = make_uint2(H2, H3);
        *(uint2*)&d_Whbf_lo[row * FOUT + 4 * ct]      = make_uint2(L0, L1);
        *(uint2*)&d_Whbf_lo[row * FOUT + 64 + 4 * ct] = make_uint2(L2, L3);
    }
}

// ============================================================================
// Kernel B1: s_i = Wh @ a_i, s_j = Wh @ a_j
// ============================================================================
__global__ __launch_bounds__(256) void s_kernel(const float* __restrict__ a_i,
                                                const float* __restrict__ a_j) {
    const int warp = threadIdx.x >> 5;
    const int lane = threadIdx.x & 31;
    const int row  = blockIdx.x * 8 + warp;
    if (row >= ROWS_TOTAL) return;

    float4 v  = ((const float4*)&d_Wh[(size_t)row * FOUT])[lane];
    float4 ai = ((const float4*)a_i)[lane];
    float4 aj = ((const float4*)a_j)[lane];
    float si = v.x * ai.x + v.y * ai.y + v.z * ai.z + v.w * ai.w;
    float sj = v.x * aj.x + v.y * aj.y + v.z * aj.z + v.w * aj.w;
    #pragma unroll
    for (int m = 16; m > 0; m >>= 1) {
        si += __shfl_xor_sync(0xffffffffu, si, m);
        sj += __shfl_xor_sync(0xffffffffu, sj, m);
    }
    if (lane == 0) { d_si[row] = si; d_sj[row] = sj; }
}

// ============================================================================
// Kernel B2: per-batch max over s_j
// ============================================================================
__global__ __launch_bounds__(256) void smax_kernel() {
    __shared__ float red[256];
    const int b = blockIdx.x;
    const int t = threadIdx.x;
    float m = -3.0e38f;
    for (int j = t; j < N_; j += 256) m = fmaxf(m, d_sj[b * N_ + j]);
    red[t] = m;
    __syncthreads();
    for (int s = 128; s > 0; s >>= 1) {
        if (t < s) red[t] = fmaxf(red[t], red[t + s]);
        __syncthreads();
    }
    if (t == 0) d_smax[b] = red[0];
}

// ============================================================================
// Kernel B3: exp tables  (factorized: p = max(E1_i F1_j, E2_i F2_j))
// ============================================================================
__global__ __launch_bounds__(256) void tables_kernel() {
    const int idx = blockIdx.x * 256 + threadIdx.x;
    if (idx >= ROWS_TOTAL) return;
    const int b = idx >> 11;
    const float sm = d_smax[b];
    const float si = d_si[idx];
    const float sj = d_sj[idx];

    const float tt = si + sm;
    const float m  = fmaxf(tt, 0.01f * tt);
    d_E12[idx] = make_float2(__expf(tt - m), __expf(0.01f * tt - m));
    const float u = sj - sm;
    d_F12[idx] = make_float2(__expf(u), __expf(0.01f * u));
}

// ============================================================================
// Kernel C: mma.sync fused  h' = softmax(...) @ Wh
// Block: 128 i x 128 o, 8 warps (warp = 16 i rows). j-chunks of 64.
// A = P (bf16 hi/lo, generated), B = Wh tile [j][o] bf16 hi/lo (cp.async).
// 3 products AhBh + AhBl + AlBh into fp32 accumulators.
// Padded strides (144/272 B) -> conflict-free ldmatrix/STS.
// ============================================================================
#define AT_STRIDE 144
#define BT_STRIDE 272
#define OFF_AH 16384
#define OFF_AL 34816
#define OFF_BH 53248
#define OFF_BL 70656
#define OFF_Z  88064
#define OFF_RZ 89088
#define SM_TOTAL_ATTN 89600

__global__ __launch_bounds__(256) void attn_mma_kernel(float* __restrict__ out) {
    extern __shared__ __align__(16) char sm[];
    const uint32_t sm32 = smem_to_u32(sm);
    const int t    = threadIdx.x;
    const int w    = t >> 5;
    const int lane = t & 31;
    const int row0 = blockIdx.x * 128;
    const int b    = row0 >> 11;
    const int i    = t & 127;       // P-gen row
    const int hh   = t >> 7;        // P-gen j-half (32 j each)

    // stage F12 table for this batch (16 KB at offset 0)
    {
        float4* dst = (float4*)sm;
        const float4* src = (const float4*)&d_F12[(size_t)b * N_];
        #pragma unroll
        for (int m = 0; m < 4; m++) dst[t + m * 256] = src[t + m * 256];
    }
    const float2 e = d_E12[row0 + i];
    const float e1 = e.x, e2 = e.y;
    float zacc = 0.0f;

    float acc[16][4];
    #pragma unroll
    for (int n = 0; n < 16; n++)
        #pragma unroll
        for (int q = 0; q < 4; q++) acc[n][q] = 0.0f;

    const float2* fsh = (const float2*)sm;
    __syncthreads();

    // per-warp ldmatrix base addresses (canonical sm80 pattern)
    const uint32_t a_base  = sm32 + OFF_AH + (w * 16 + (lane & 15)) * AT_STRIDE
                             + ((lane >> 4) << 4);
    const uint32_t b_base  = sm32 + OFF_BH + (lane & 15) * BT_STRIDE
                             + ((lane >> 4) << 4);

    #pragma unroll 1
    for (int c = 0; c < 32; c++) {
        const int j0 = c * 64;
        __syncthreads();   // previous chunk's reads done before overwrite

        // ---- stage B tiles via cp.async: 64 j x 128 o bf16, hi+lo ----
        {
            const __nv_bfloat16* gh = &d_Whbf_hi[(size_t)(b * N_ + j0) * FOUT];
            const __nv_bfloat16* gl = &d_Whbf_lo[(size_t)(b * N_ + j0) * FOUT];
            #pragma unroll
            for (int m = 0; m < 4; m++) {
                int idx = t + m * 256;          // 0..1023
                int j = idx >> 4, cq = idx & 15;
                uint32_t ds = (uint32_t)(j * BT_STRIDE + cq * 16);
                cp16(sm32 + OFF_BH + ds, gh + (size_t)j * FOUT + cq * 8);
                cp16(sm32 + OFF_BL + ds, gl + (size_t)j * FOUT + cq * 8);
            }
            CP_COMMIT();
        }

        // ---- generate A = P hi/lo [128 i][64 j] (overlaps cp.async) ----
        {
            char* ah = sm + OFF_AH;
            char* al = sm + OFF_AL;
            #pragma unroll
            for (int q = 0; q < 4; q++) {
                int jl = hh * 32 + q * 8;
                const float4* fp = (const float4*)&fsh[j0 + jl];
                float4 fa = fp[0], fb = fp[1], fc = fp[2], fd = fp[3];
                float p0 = fmaxf(e1 * fa.x, e2 * fa.y);
                float p1 = fmaxf(e1 * fa.z, e2 * fa.w);
                float p2 = fmaxf(e1 * fb.x, e2 * fb.y);
                float p3 = fmaxf(e1 * fb.z, e2 * fb.w);
                float p4 = fmaxf(e1 * fc.x, e2 * fc.y);
                float p5 = fmaxf(e1 * fc.z, e2 * fc.w);
                float p6 = fmaxf(e1 * fd.x, e2 * fd.y);
                float p7 = fmaxf(e1 * fd.z, e2 * fd.w);
                zacc += ((p0 + p1) + (p2 + p3)) + ((p4 + p5) + (p6 + p7));
                uint32_t h01, h23, h45, h67;
                CVTPK(h01, p0, p1); CVTPK(h23, p2, p3);
                CVTPK(h45, p4, p5); CVTPK(h67, p6, p7);
                float r0 = p0 - loF(h01), r1 = p1 - hiF(h01);
                float r2 = p2 - loF(h23), r3 = p3 - hiF(h23);
                float r4 = p4 - loF(h45), r5 = p5 - hiF(h45);
                float r6 = p6 - loF(h67), r7 = p7 - hiF(h67);
                uint32_t l01, l23, l45, l67;
                CVTPK(l01, r0, r1); CVTPK(l23, r2, r3);
                CVTPK(l45, r4, r5); CVTPK(l67, r6, r7);
                uint32_t off = (uint32_t)(i * AT_STRIDE + jl * 2);
                *(uint4*)(ah + off) = make_uint4(h01, h23, h45, h67);
                *(uint4*)(al + off) = make_uint4(l01, l23, l45, l67);
            }
        }
        CP_WAIT0();
        __syncthreads();

        // ---- compute: 4 k16-steps x 16 n-tiles x 3 products ----
        #pragma unroll
        for (int kc = 0; kc < 4; kc++) {
            uint32_t ah0, ah1, ah2, ah3, al0, al1, al2, al3;
            ldsm4(ah0, ah1, ah2, ah3, a_base + kc * 32);
            ldsm4(al0, al1, al2, al3, a_base + (OFF_AL - OFF_AH) + kc * 32);
            const uint32_t bk = b_base + kc * 16 * BT_STRIDE;
            #pragma unroll
            for (int ntp = 0; ntp < 8; ntp++) {
                uint32_t bh0, bh1, bh2, bh3, bl0, bl1, bl2, bl3;
                ldsm4t(bh0, bh1, bh2, bh3, bk + ntp * 32);
                ldsm4t(bl0, bl1, bl2, bl3, bk + (OFF_BL - OFF_BH) + ntp * 32);
                mma16816(acc[2 * ntp],     ah0, ah1, ah2, ah3, bh0, bh1);
                mma16816(acc[2 * ntp],     ah0, ah1, ah2, ah3, bl0, bl1);
                mma16816(acc[2 * ntp],     al0, al1, al2, al3, bh0, bh1);
                mma16816(acc[2 * ntp + 1], ah0, ah1, ah2, ah3, bh2, bh3);
                mma16816(acc[2 * ntp + 1], ah0, ah1, ah2, ah3, bl2, bl3);
                mma16816(acc[2 * ntp + 1], al0, al1, al2, al3, bh2, bh3);
            }
        }
    }

    // ---- Z reduction ----
    ((float*)(sm + OFF_Z))[hh * 128 + i] = zacc;
    __syncthreads();
    if (t < 128) {
        float Z = ((float*)(sm + OFF_Z))[t] + ((float*)(sm + OFF_Z))[128 + t];
        ((float*)(sm + OFF_RZ))[t] = 1.0f / Z;
    }
    __syncthreads();

    // ---- epilogue: normalize + store ----
    {
        const int r0 = w * 16 + (lane >> 2);
        const int r1 = r0 + 8;
        const float rz0 = ((float*)(sm + OFF_RZ))[r0];
        const float rz1 = ((float*)(sm + OFF_RZ))[r1];
        float* o0 = &out[(size_t)(row0 + r0) * FOUT];
        float* o1 = &out[(size_t)(row0 + r1) * FOUT];
        #pragma unroll
        for (int nt = 0; nt < 16; nt++) {
            const int cc = nt * 8 + (lane & 3) * 2;
            *(float2*)&o0[cc] = make_float2(acc[nt][0] * rz0, acc[nt][1] * rz0);
            *(float2*)&o1[cc] = make_float2(acc[nt][2] * rz1, acc[nt][3] * rz1);
        }
    }
}

// ============================================================================
// launch
// ============================================================================
extern "C" void kernel_launch(void* const* d_in, const int* in_sizes, int n_in,
                              void* d_out, int out_size) {
    const float* h    = (const float*)d_in[0];  // [8,2048,256]
    const float* W_fc = (const float*)d_in[1];  // [256,128]
    const float* a_i  = (const float*)d_in[2];  // [128]
    const float* a_j  = (const float*)d_in[3];  // [128]
    float* out = (float*)d_out;                 // [8,2048,128]

    cudaFuncSetAttribute(attn_mma_kernel,
                         cudaFuncAttributeMaxDynamicSharedMemorySize, SM_TOTAL_ATTN);

    wh_kernel<<<ROWS_TOTAL / 64, 256>>>(h, W_fc);
    s_kernel<<<ROWS_TOTAL / 8, 256>>>(a_i, a_j);
    smax_kernel<<<B_, 256>>>();
    tables_kernel<<<ROWS_TOTAL / 256, 256>>>();
    attn_mma_kernel<<<ROWS_TOTAL / 128, 256, SM_TOTAL_ATTN>>>(out);
}

// round 10
// speedup vs baseline: 20.9883x; 1.1466x over previous
#include <cuda_runtime.h>
#include <cuda_bf16.h>
#include <cstdint>

#define B_   8
#define N_   2048
#define FIN  256
#define FOUT 128
#define ROWS_TOTAL (B_ * N_)   // 16384

// -------- static device scratch --------
__device__ __align__(16) __nv_bfloat16 d_Whbf_hi[(size_t)ROWS_TOTAL * FOUT]; // 4 MB [row][o]
__device__ __align__(16) __nv_bfloat16 d_Whbf_lo[(size_t)ROWS_TOTAL * FOUT]; // 4 MB
__device__ float  d_si[ROWS_TOTAL];
__device__ float  d_sj[ROWS_TOTAL];
__device__ __align__(16) float2 d_E12[ROWS_TOTAL];
__device__ __align__(16) float2 d_F12[ROWS_TOTAL];

// bf16 pack/split helpers. CVTPK(res,a,b): res = bf16x2 {lo=a, hi=b} (memory order a,b)
#define CVTPK(res, a, b) \
    asm("cvt.rn.satfinite.bf16x2.f32 %0, %1, %2;" : "=r"(res) : "f"(b), "f"(a))
__device__ __forceinline__ float loF(uint32_t h) { return __uint_as_float(h << 16); }
__device__ __forceinline__ float hiF(uint32_t h) { return __uint_as_float(h & 0xffff0000u); }

__device__ __forceinline__ uint32_t smem_to_u32(const void* p) {
    uint32_t a;
    asm("{ .reg .u64 t; cvta.to.shared.u64 t, %1; cvt.u32.u64 %0, t; }" : "=r"(a) : "l"(p));
    return a;
}
__device__ __forceinline__ void cp16(uint32_t s, const void* g) {
    asm volatile("cp.async.cg.shared.global [%0], [%1], 16;" :: "r"(s), "l"(g) : "memory");
}
#define CP_COMMIT() asm volatile("cp.async.commit_group;" ::: "memory")
#define CP_WAIT0()  asm volatile("cp.async.wait_group 0;" ::: "memory")

__device__ __forceinline__ void ldsm4(uint32_t& r0, uint32_t& r1, uint32_t& r2,
                                      uint32_t& r3, uint32_t a) {
    asm volatile("ldmatrix.sync.aligned.m8n8.x4.shared.b16 {%0,%1,%2,%3}, [%4];"
                 : "=r"(r0), "=r"(r1), "=r"(r2), "=r"(r3) : "r"(a));
}
__device__ __forceinline__ void ldsm4t(uint32_t& r0, uint32_t& r1, uint32_t& r2,
                                       uint32_t& r3, uint32_t a) {
    asm volatile("ldmatrix.sync.aligned.m8n8.x4.trans.shared.b16 {%0,%1,%2,%3}, [%4];"
                 : "=r"(r0), "=r"(r1), "=r"(r2), "=r"(r3) : "r"(a));
}
__device__ __forceinline__ void mma16816(float* c, uint32_t a0, uint32_t a1,
                                         uint32_t a2, uint32_t a3,
                                         uint32_t b0, uint32_t b1) {
    asm volatile("mma.sync.aligned.m16n8k16.row.col.f32.bf16.bf16.f32 "
                 "{%0,%1,%2,%3}, {%4,%5,%6,%7}, {%8,%9}, {%0,%1,%2,%3};"
                 : "+f"(c[0]), "+f"(c[1]), "+f"(c[2]), "+f"(c[3])
                 : "r"(a0), "r"(a1), "r"(a2), "r"(a3), "r"(b0), "r"(b1));
}

#define AT_STRIDE 144   // bf16 [i][k64] row stride bytes (128 + 16 pad)
#define BT_STRIDE 272   // bf16 [k/j][o128] row stride bytes (256 + 16 pad)

// ============================================================================
// Kernel A (tensorized): Wh = h @ W_fc, bf16-split 3-product mma.sync.
// Block: 128 rows x 128 cols; K=256 in 4 chunks of 64.
// h and W are split to bf16 hi/lo on the fly during staging.
// Epilogue: writes Whbf hi/lo AND computes s_i, s_j (no fp32 Wh anywhere).
// ============================================================================
#define WH_AH 0
#define WH_AL 18432
#define WH_BH 36864
#define WH_BL 54272
#define WH_AIJ 71680              // a_i[128], a_j[128]
#define SM_TOTAL_WH 72704

__global__ __launch_bounds__(256) void wh_mma_kernel(const float* __restrict__ h,
                                                     const float* __restrict__ W,
                                                     const float* __restrict__ a_i,
                                                     const float* __restrict__ a_j) {
    extern __shared__ __align__(16) char sm[];
    const uint32_t sm32 = smem_to_u32(sm);
    const int t    = threadIdx.x;
    const int w    = t >> 5;
    const int lane = t & 31;
    const int row0 = blockIdx.x * 128;

    float acc[16][4];
    #pragma unroll
    for (int n = 0; n < 16; n++)
        #pragma unroll
        for (int q = 0; q < 4; q++) acc[n][q] = 0.0f;

    if (t < 128) {
        ((float*)(sm + WH_AIJ))[t]       = a_i[t];
        ((float*)(sm + WH_AIJ))[128 + t] = a_j[t];
    }

    const uint32_t a_base = sm32 + WH_AH + (w * 16 + (lane & 15)) * AT_STRIDE
                            + ((lane >> 4) << 4);
    const uint32_t b_base = sm32 + WH_BH + (lane & 15) * BT_STRIDE
                            + ((lane >> 4) << 4);

    #pragma unroll 1
    for (int c = 0; c < 4; c++) {
        const int k0 = c * 64;
        __syncthreads();
        // ---- stage A = h[128 x 64] split hi/lo ----
        #pragma unroll
        for (int m = 0; m < 8; m++) {
            int idx = t + m * 256;          // 0..2047 float4
            int i = idx >> 4, kq = idx & 15;
            float4 v = *(const float4*)&h[(size_t)(row0 + i) * FIN + k0 + kq * 4];
            uint32_t H0, H1;
            CVTPK(H0, v.x, v.y); CVTPK(H1, v.z, v.w);
            float l0 = v.x - loF(H0), l1 = v.y - hiF(H0);
            float l2 = v.z - loF(H1), l3 = v.w - hiF(H1);
            uint32_t L0, L1;
            CVTPK(L0, l0, l1); CVTPK(L1, l2, l3);
            uint32_t off = (uint32_t)(i * AT_STRIDE + kq * 8);
            *(uint2*)(sm + WH_AH + off) = make_uint2(H0, H1);
            *(uint2*)(sm + WH_AL + off) = make_uint2(L0, L1);
        }
        // ---- stage B = W[64 x 128] split hi/lo ----
        #pragma unroll
        for (int m = 0; m < 8; m++) {
            int idx = t + m * 256;
            int k = idx >> 5, cq = idx & 31;
            float4 v = *(const float4*)&W[(size_t)(k0 + k) * FOUT + cq * 4];
            uint32_t H0, H1;
            CVTPK(H0, v.x, v.y); CVTPK(H1, v.z, v.w);
            float l0 = v.x - loF(H0), l1 = v.y - hiF(H0);
            float l2 = v.z - loF(H1), l3 = v.w - hiF(H1);
            uint32_t L0, L1;
            CVTPK(L0, l0, l1); CVTPK(L1, l2, l3);
            uint32_t off = (uint32_t)(k * BT_STRIDE + cq * 8);
            *(uint2*)(sm + WH_BH + off) = make_uint2(H0, H1);
            *(uint2*)(sm + WH_BL + off) = make_uint2(L0, L1);
        }
        __syncthreads();

        #pragma unroll
        for (int kc = 0; kc < 4; kc++) {
            uint32_t ah0, ah1, ah2, ah3, al0, al1, al2, al3;
            ldsm4(ah0, ah1, ah2, ah3, a_base + kc * 32);
            ldsm4(al0, al1, al2, al3, a_base + (WH_AL - WH_AH) + kc * 32);
            const uint32_t bk = b_base + kc * 16 * BT_STRIDE;
            #pragma unroll
            for (int ntp = 0; ntp < 8; ntp++) {
                uint32_t bh0, bh1, bh2, bh3, bl0, bl1, bl2, bl3;
                ldsm4t(bh0, bh1, bh2, bh3, bk + ntp * 32);
                ldsm4t(bl0, bl1, bl2, bl3, bk + (WH_BL - WH_BH) + ntp * 32);
                mma16816(acc[2 * ntp],     ah0, ah1, ah2, ah3, bh0, bh1);
                mma16816(acc[2 * ntp],     ah0, ah1, ah2, ah3, bl0, bl1);
                mma16816(acc[2 * ntp],     al0, al1, al2, al3, bh0, bh1);
                mma16816(acc[2 * ntp + 1], ah0, ah1, ah2, ah3, bh2, bh3);
                mma16816(acc[2 * ntp + 1], ah0, ah1, ah2, ah3, bl2, bl3);
                mma16816(acc[2 * ntp + 1], al0, al1, al2, al3, bh2, bh3);
            }
        }
    }

    // ---- epilogue: bf16 hi/lo store + s_i/s_j ----
    const int r0 = w * 16 + (lane >> 2);
    const int r1 = r0 + 8;
    const float* aish = (const float*)(sm + WH_AIJ);
    const float* ajsh = (const float*)(sm + WH_AIJ) + 128;

    float si0 = 0.f, si1 = 0.f, sj0 = 0.f, sj1 = 0.f;
    #pragma unroll
    for (int nt = 0; nt < 16; nt++) {
        const int cc = nt * 8 + (lane & 3) * 2;
        // hi/lo split stores
        uint32_t Hi0, Hi1;
        CVTPK(Hi0, acc[nt][0], acc[nt][1]);
        CVTPK(Hi1, acc[nt][2], acc[nt][3]);
        float u0 = acc[nt][0] - loF(Hi0), u1 = acc[nt][1] - hiF(Hi0);
        float u2 = acc[nt][2] - loF(Hi1), u3 = acc[nt][3] - hiF(Hi1);
        uint32_t Lo0, Lo1;
        CVTPK(Lo0, u0, u1); CVTPK(Lo1, u2, u3);
        *(uint32_t*)&d_Whbf_hi[(size_t)(row0 + r0) * FOUT + cc] = Hi0;
        *(uint32_t*)&d_Whbf_hi[(size_t)(row0 + r1) * FOUT + cc] = Hi1;
        *(uint32_t*)&d_Whbf_lo[(size_t)(row0 + r0) * FOUT + cc] = Lo0;
        *(uint32_t*)&d_Whbf_lo[(size_t)(row0 + r1) * FOUT + cc] = Lo1;
        // s partials
        float ai0 = aish[cc], ai1 = aish[cc + 1];
        float aj0 = ajsh[cc], aj1 = ajsh[cc + 1];
        si0 += acc[nt][0] * ai0 + acc[nt][1] * ai1;
        sj0 += acc[nt][0] * aj0 + acc[nt][1] * aj1;
        si1 += acc[nt][2] * ai0 + acc[nt][3] * ai1;
        sj1 += acc[nt][2] * aj0 + acc[nt][3] * aj1;
    }
    #pragma unroll
    for (int m = 1; m <= 2; m <<= 1) {
        si0 += __shfl_xor_sync(0xffffffffu, si0, m);
        sj0 += __shfl_xor_sync(0xffffffffu, sj0, m);
        si1 += __shfl_xor_sync(0xffffffffu, si1, m);
        sj1 += __shfl_xor_sync(0xffffffffu, sj1, m);
    }
    if ((lane & 3) == 0) {
        d_si[row0 + r0] = si0;
        d_sj[row0 + r0] = sj0;
        d_si[row0 + r1] = si1;
        d_sj[row0 + r1] = sj1;
    }
}

// ============================================================================
// Kernel B: per-batch smax + exp tables (fused), 1 block per batch
// p_ij = exp(lrelu(si+sj) - m_i) = max(E1_i F1_j, E2_i F2_j)
// ============================================================================
__global__ __launch_bounds__(256) void tables8_kernel() {
    __shared__ float red[256];
    const int b = blockIdx.x;
    const int t = threadIdx.x;
    float m = -3.0e38f;
    for (int j = t; j < N_; j += 256) m = fmaxf(m, d_sj[b * N_ + j]);
    red[t] = m;
    __syncthreads();
    for (int s = 128; s > 0; s >>= 1) {
        if (t < s) red[t] = fmaxf(red[t], red[t + s]);
        __syncthreads();
    }
    const float sm_ = red[0];

    for (int idx = t; idx < N_; idx += 256) {
        const int g = b * N_ + idx;
        const float si = d_si[g];
        const float sj = d_sj[g];
        const float tt = si + sm_;
        const float mm = fmaxf(tt, 0.01f * tt);
        d_E12[g] = make_float2(__expf(tt - mm), __expf(0.01f * tt - mm));
        const float u = sj - sm_;
        d_F12[g] = make_float2(__expf(u), __expf(0.01f * u));
    }
}

// ============================================================================
// Kernel C: mma.sync fused  h' = softmax(...) @ Wh   — double-buffered
// Block: 128 i x 128 o, 8 warps. j-chunks of 64, A/B smem buffers x2.
// Per chunk: cp.async B(c+1) + gen A(c+1) overlap compute(c).
// ============================================================================
#define OFF_F12 0
#define OFF_AH  16384               // 2 x 18432
#define OFF_AL  53248               // 2 x 18432
#define OFF_BH  90112               // 2 x 17408
#define OFF_BL  124928              // 2 x 17408
#define OFF_Z   159744
#define OFF_RZ  160768
#define SM_TOTAL_ATTN 161280

__global__ __launch_bounds__(256) void attn_mma_kernel(float* __restrict__ out) {
    extern __shared__ __align__(16) char sm[];
    const uint32_t sm32 = smem_to_u32(sm);
    const int t    = threadIdx.x;
    const int w    = t >> 5;
    const int lane = t & 31;
    const int row0 = blockIdx.x * 128;
    const int b    = row0 >> 11;
    const int i    = t & 127;       // P-gen row
    const int hh   = t >> 7;        // P-gen j-half (32 j each)

    // stage F12 table for this batch (16 KB)
    {
        float4* dst = (float4*)(sm + OFF_F12);
        const float4* src = (const float4*)&d_F12[(size_t)b * N_];
        #pragma unroll
        for (int m = 0; m < 4; m++) dst[t + m * 256] = src[t + m * 256];
    }
    const float2 e = d_E12[row0 + i];
    const float e1 = e.x, e2 = e.y;
    float zacc = 0.0f;
    const float2* fsh = (const float2*)(sm + OFF_F12);

    float acc[16][4];
    #pragma unroll
    for (int n = 0; n < 16; n++)
        #pragma unroll
        for (int q = 0; q < 4; q++) acc[n][q] = 0.0f;

    const uint32_t a_base = sm32 + OFF_AH + (w * 16 + (lane & 15)) * AT_STRIDE
                            + ((lane >> 4) << 4);
    const uint32_t b_base = sm32 + OFF_BH + (lane & 15) * BT_STRIDE
                            + ((lane >> 4) << 4);

    const __nv_bfloat16* gWhi = &d_Whbf_hi[(size_t)b * N_ * FOUT];
    const __nv_bfloat16* gWlo = &d_Whbf_lo[(size_t)b * N_ * FOUT];

    // ---- stage_B lambda-ish macros ----
#define STAGE_B(CH, S) do { \
        const int _j0 = (CH) * 64; \
        const uint32_t _bh = sm32 + OFF_BH + (S) * 17408; \
        const uint32_t _bl = sm32 + OFF_BL + (S) * 17408; \
        _Pragma("unroll") \
        for (int m = 0; m < 4; m++) { \
            int idx = t + m * 256; \
            int j = idx >> 4, cq = idx & 15; \
            uint32_t ds = (uint32_t)(j * BT_STRIDE + cq * 16); \
            cp16(_bh + ds, gWhi + (size_t)(_j0 + j) * FOUT + cq * 8); \
            cp16(_bl + ds, gWlo + (size_t)(_j0 + j) * FOUT + cq * 8); \
        } \
        CP_COMMIT(); \
    } while (0)

#define GEN_A(CH, S) do { \
        const int _j0 = (CH) * 64; \
        char* _ah = sm + OFF_AH + (S) * 18432; \
        char* _al = sm + OFF_AL + (S) * 18432; \
        _Pragma("unroll") \
        for (int q = 0; q < 4; q++) { \
            int jl = hh * 32 + q * 8; \
            const float4* fp = (const float4*)&fsh[_j0 + jl]; \
            float4 fa = fp[0], fb = fp[1], fc = fp[2], fd = fp[3]; \
            float p0 = fmaxf(e1 * fa.x, e2 * fa.y); \
            float p1 = fmaxf(e1 * fa.z, e2 * fa.w); \
            float p2 = fmaxf(e1 * fb.x, e2 * fb.y); \
            float p3 = fmaxf(e1 * fb.z, e2 * fb.w); \
            float p4 = fmaxf(e1 * fc.x, e2 * fc.y); \
            float p5 = fmaxf(e1 * fc.z, e2 * fc.w); \
            float p6 = fmaxf(e1 * fd.x, e2 * fd.y); \
            float p7 = fmaxf(e1 * fd.z, e2 * fd.w); \
            zacc += ((p0 + p1) + (p2 + p3)) + ((p4 + p5) + (p6 + p7)); \
            uint32_t h01, h23, h45, h67; \
            CVTPK(h01, p0, p1); CVTPK(h23, p2, p3); \
            CVTPK(h45, p4, p5); CVTPK(h67, p6, p7); \
            float r0_ = p0 - loF(h01), r1_ = p1 - hiF(h01); \
            float r2_ = p2 - loF(h23), r3_ = p3 - hiF(h23); \
            float r4_ = p4 - loF(h45), r5_ = p5 - hiF(h45); \
            float r6_ = p6 - loF(h67), r7_ = p7 - hiF(h67); \
            uint32_t l01, l23, l45, l67; \
            CVTPK(l01, r0_, r1_); CVTPK(l23, r2_, r3_); \
            CVTPK(l45, r4_, r5_); CVTPK(l67, r6_, r7_); \
            uint32_t off = (uint32_t)(i * AT_STRIDE + jl * 2); \
            *(uint4*)(_ah + off) = make_uint4(h01, h23, h45, h67); \
            *(uint4*)(_al + off) = make_uint4(l01, l23, l45, l67); \
        } \
    } while (0)

    __syncthreads();        // F12 visible
    STAGE_B(0, 0);
    GEN_A(0, 0);

    #pragma unroll 1
    for (int c = 0; c < 32; c++) {
        const int s = c & 1;
        CP_WAIT0();          // B(c) arrived (B(c+1) not yet issued)
        __syncthreads();     // all warps done compute(c-1); A(c)/B(c) visible
        if (c + 1 < 32) {
            STAGE_B(c + 1, s ^ 1);   // overlaps compute(c)
            GEN_A(c + 1, s ^ 1);
        }

        const uint32_t ah_b = a_base + s * 18432;
        const uint32_t al_b = a_base + (OFF_AL - OFF_AH) + s * 18432;
        const uint32_t bh_b = b_base + s * 17408;
        const uint32_t bl_b = b_base + (OFF_BL - OFF_BH) + s * 17408;
        #pragma unroll
        for (int kc = 0; kc < 4; kc++) {
            uint32_t ah0, ah1, ah2, ah3, al0, al1, al2, al3;
            ldsm4(ah0, ah1, ah2, ah3, ah_b + kc * 32);
            ldsm4(al0, al1, al2, al3, al_b + kc * 32);
            const uint32_t bko = kc * 16 * BT_STRIDE;
            #pragma unroll
            for (int ntp = 0; ntp < 8; ntp++) {
                uint32_t bh0, bh1, bh2, bh3, bl0, bl1, bl2, bl3;
                ldsm4t(bh0, bh1, bh2, bh3, bh_b + bko + ntp * 32);
                ldsm4t(bl0, bl1, bl2, bl3, bl_b + bko + ntp * 32);
                mma16816(acc[2 * ntp],     ah0, ah1, ah2, ah3, bh0, bh1);
                mma16816(acc[2 * ntp],     ah0, ah1, ah2, ah3, bl0, bl1);
                mma16816(acc[2 * ntp],     al0, al1, al2, al3, bh0, bh1);
                mma16816(acc[2 * ntp + 1], ah0, ah1, ah2, ah3, bh2, bh3);
                mma16816(acc[2 * ntp + 1], ah0, ah1, ah2, ah3, bl2, bl3);
                mma16816(acc[2 * ntp + 1], al0, al1, al2, al3, bh2, bh3);
            }
        }
    }

    // ---- Z reduction ----
    ((float*)(sm + OFF_Z))[hh * 128 + i] = zacc;
    __syncthreads();
    if (t < 128) {
        float Z = ((float*)(sm + OFF_Z))[t] + ((float*)(sm + OFF_Z))[128 + t];
        ((float*)(sm + OFF_RZ))[t] = 1.0f / Z;
    }
    __syncthreads();

    // ---- epilogue: normalize + store ----
    {
        const int r0 = w * 16 + (lane >> 2);
        const int r1 = r0 + 8;
        const float rz0 = ((float*)(sm + OFF_RZ))[r0];
        const float rz1 = ((float*)(sm + OFF_RZ))[r1];
        float* o0 = &out[(size_t)(row0 + r0) * FOUT];
        float* o1 = &out[(size_t)(row0 + r1) * FOUT];
        #pragma unroll
        for (int nt = 0; nt < 16; nt++) {
            const int cc = nt * 8 + (lane & 3) * 2;
            *(float2*)&o0[cc] = make_float2(acc[nt][0] * rz0, acc[nt][1] * rz0);
            *(float2*)&o1[cc] = make_float2(acc[nt][2] * rz1, acc[nt][3] * rz1);
        }
    }
#undef STAGE_B
#undef GEN_A
}

// ============================================================================
// launch
// ============================================================================
extern "C" void kernel_launch(void* const* d_in, const int* in_sizes, int n_in,
                              void* d_out, int out_size) {
    const float* h    = (const float*)d_in[0];  // [8,2048,256]
    const float* W_fc = (const float*)d_in[1];  // [256,128]
    const float* a_i  = (const float*)d_in[2];  // [128]
    const float* a_j  = (const float*)d_in[3];  // [128]
    float* out = (float*)d_out;                 // [8,2048,128]

    cudaFuncSetAttribute(wh_mma_kernel,
                         cudaFuncAttributeMaxDynamicSharedMemorySize, SM_TOTAL_WH);
    cudaFuncSetAttribute(attn_mma_kernel,
                         cudaFuncAttributeMaxDynamicSharedMemorySize, SM_TOTAL_ATTN);

    wh_mma_kernel<<<ROWS_TOTAL / 128, 256, SM_TOTAL_WH>>>(h, W_fc, a_i, a_j);
    tables8_kernel<<<B_, 256>>>();
    attn_mma_kernel<<<ROWS_TOTAL / 128, 256, SM_TOTAL_ATTN>>>(out);
}

// round 11
// speedup vs baseline: 22.0340x; 1.0498x over previous
#include <cuda_runtime.h>
#include <cuda_bf16.h>
#include <cstdint>

#define B_   8
#define N_   2048
#define FIN  256
#define FOUT 128
#define ROWS_TOTAL (B_ * N_)   // 16384

// -------- static device scratch --------
__device__ __align__(16) __nv_bfloat16 d_Whbf_hi[(size_t)ROWS_TOTAL * FOUT]; // 4 MB [row][o]
__device__ __align__(16) __nv_bfloat16 d_Whbf_lo[(size_t)ROWS_TOTAL * FOUT]; // 4 MB
__device__ float  d_si[ROWS_TOTAL];
__device__ float  d_sj[ROWS_TOTAL];
__device__ __align__(16) float2 d_E12[ROWS_TOTAL];
__device__ __align__(16) float2 d_F12[ROWS_TOTAL];
__device__ unsigned d_smax_bits[B_];   // order-preserving float encoding; zero-init = -inf-ish
                                       // atomicMax is idempotent -> deterministic across replays

// bf16 pack/split helpers. CVTPK(res,a,b): res = bf16x2 {lo=a, hi=b} (memory order a,b)
#define CVTPK(res, a, b) \
    asm("cvt.rn.satfinite.bf16x2.f32 %0, %1, %2;" : "=r"(res) : "f"(b), "f"(a))
__device__ __forceinline__ float loF(uint32_t h) { return __uint_as_float(h << 16); }
__device__ __forceinline__ float hiF(uint32_t h) { return __uint_as_float(h & 0xffff0000u); }

__device__ __forceinline__ uint32_t smem_to_u32(const void* p) {
    uint32_t a;
    asm("{ .reg .u64 t; cvta.to.shared.u64 t, %1; cvt.u32.u64 %0, t; }" : "=r"(a) : "l"(p));
    return a;
}
__device__ __forceinline__ void cp16(uint32_t s, const void* g) {
    asm volatile("cp.async.cg.shared.global [%0], [%1], 16;" :: "r"(s), "l"(g) : "memory");
}
#define CP_COMMIT() asm volatile("cp.async.commit_group;" ::: "memory")
#define CP_WAIT0()  asm volatile("cp.async.wait_group 0;" ::: "memory")

__device__ __forceinline__ void ldsm4(uint32_t& r0, uint32_t& r1, uint32_t& r2,
                                      uint32_t& r3, uint32_t a) {
    asm volatile("ldmatrix.sync.aligned.m8n8.x4.shared.b16 {%0,%1,%2,%3}, [%4];"
                 : "=r"(r0), "=r"(r1), "=r"(r2), "=r"(r3) : "r"(a));
}
__device__ __forceinline__ void ldsm4t(uint32_t& r0, uint32_t& r1, uint32_t& r2,
                                       uint32_t& r3, uint32_t a) {
    asm volatile("ldmatrix.sync.aligned.m8n8.x4.trans.shared.b16 {%0,%1,%2,%3}, [%4];"
                 : "=r"(r0), "=r"(r1), "=r"(r2), "=r"(r3) : "r"(a));
}
__device__ __forceinline__ void mma16816(float* c, uint32_t a0, uint32_t a1,
                                         uint32_t a2, uint32_t a3,
                                         uint32_t b0, uint32_t b1) {
    asm volatile("mma.sync.aligned.m16n8k16.row.col.f32.bf16.bf16.f32 "
                 "{%0,%1,%2,%3}, {%4,%5,%6,%7}, {%8,%9}, {%0,%1,%2,%3};"
                 : "+f"(c[0]), "+f"(c[1]), "+f"(c[2]), "+f"(c[3])
                 : "r"(a0), "r"(a1), "r"(a2), "r"(a3), "r"(b0), "r"(b1));
}

// order-preserving float->uint key
__device__ __forceinline__ unsigned fkey(float f) {
    unsigned b = __float_as_uint(f);
    return (b & 0x80000000u) ? ~b : (b | 0x80000000u);
}
__device__ __forceinline__ float funkey(unsigned k) {
    unsigned b = (k & 0x80000000u) ? (k & 0x7fffffffu) : ~k;
    return __uint_as_float(b);
}

#define AT_STRIDE 144   // bf16 [i][k64] row stride bytes (128 + 16 pad)
#define BT_STRIDE 272   // bf16 [k/j][o128] row stride bytes (256 + 16 pad)

// ============================================================================
// Kernel A: Wh = h @ W_fc, bf16-split 3-product mma.sync.
// Block: 64 rows x 128 cols; grid 256 -> 2 CTAs/SM. 8 warps = 4 rowgrp x 2 colgrp.
// Epilogue: Whbf hi/lo stores + s_i/s_j + per-batch sj-max via atomicMax.
// ============================================================================
#define WH_AH  0        // [64 i][64 k] hi  9216
#define WH_AL  9216     // lo               9216
#define WH_BH  18432    // [64 k][128 o] hi 17408
#define WH_BL  35840    // lo               17408
#define WH_AIJ 53248    // a_i[128], a_j[128] fp32
#define WH_PSI 54272    // [2][64]
#define WH_PSJ 54784    // [2][64]
#define WH_WMX 55296    // [2]
#define SM_TOTAL_WH 55424

__global__ __launch_bounds__(256, 2) void wh_mma_kernel(const float* __restrict__ h,
                                                        const float* __restrict__ W,
                                                        const float* __restrict__ a_i,
                                                        const float* __restrict__ a_j) {
    extern __shared__ __align__(16) char sm[];
    const uint32_t sm32 = smem_to_u32(sm);
    const int t      = threadIdx.x;
    const int w      = t >> 5;
    const int lane   = t & 31;
    const int wg_row = w >> 1;          // 0..3 -> i base 16*wg_row
    const int wg_col = w & 1;           // 0..1 -> o base 64*wg_col
    const int row0   = blockIdx.x * 64;
    const int b      = row0 >> 11;

    float acc[8][4];
    #pragma unroll
    for (int n = 0; n < 8; n++)
        #pragma unroll
        for (int q = 0; q < 4; q++) acc[n][q] = 0.0f;

    if (t < 128) {
        ((float*)(sm + WH_AIJ))[t]       = a_i[t];
        ((float*)(sm + WH_AIJ))[128 + t] = a_j[t];
    }

    const uint32_t a_base = sm32 + WH_AH + (wg_row * 16 + (lane & 15)) * AT_STRIDE
                            + ((lane >> 4) << 4);
    const uint32_t b_base = sm32 + WH_BH + (lane & 15) * BT_STRIDE
                            + ((lane >> 4) << 4) + wg_col * 128;

    #pragma unroll 1
    for (int c = 0; c < 4; c++) {
        const int k0 = c * 64;
        __syncthreads();
        // ---- stage A = h[64 x 64] split hi/lo ----
        #pragma unroll
        for (int m = 0; m < 4; m++) {
            int idx = t + m * 256;          // 0..1023 float4
            int i = idx >> 4, kq = idx & 15;
            float4 v = *(const float4*)&h[(size_t)(row0 + i) * FIN + k0 + kq * 4];
            uint32_t H0, H1;
            CVTPK(H0, v.x, v.y); CVTPK(H1, v.z, v.w);
            float l0 = v.x - loF(H0), l1 = v.y - hiF(H0);
            float l2 = v.z - loF(H1), l3 = v.w - hiF(H1);
            uint32_t L0, L1;
            CVTPK(L0, l0, l1); CVTPK(L1, l2, l3);
            uint32_t off = (uint32_t)(i * AT_STRIDE + kq * 8);
            *(uint2*)(sm + WH_AH + off) = make_uint2(H0, H1);
            *(uint2*)(sm + WH_AL + off) = make_uint2(L0, L1);
        }
        // ---- stage B = W[64 x 128] split hi/lo ----
        #pragma unroll
        for (int m = 0; m < 8; m++) {
            int idx = t + m * 256;          // 0..2047 float4
            int k = idx >> 5, cq = idx & 31;
            float4 v = *(const float4*)&W[(size_t)(k0 + k) * FOUT + cq * 4];
            uint32_t H0, H1;
            CVTPK(H0, v.x, v.y); CVTPK(H1, v.z, v.w);
            float l0 = v.x - loF(H0), l1 = v.y - hiF(H0);
            float l2 = v.z - loF(H1), l3 = v.w - hiF(H1);
            uint32_t L0, L1;
            CVTPK(L0, l0, l1); CVTPK(L1, l2, l3);
            uint32_t off = (uint32_t)(k * BT_STRIDE + cq * 8);
            *(uint2*)(sm + WH_BH + off) = make_uint2(H0, H1);
            *(uint2*)(sm + WH_BL + off) = make_uint2(L0, L1);
        }
        __syncthreads();

        #pragma unroll
        for (int kc = 0; kc < 4; kc++) {
            uint32_t ah0, ah1, ah2, ah3, al0, al1, al2, al3;
            ldsm4(ah0, ah1, ah2, ah3, a_base + kc * 32);
            ldsm4(al0, al1, al2, al3, a_base + (WH_AL - WH_AH) + kc * 32);
            const uint32_t bko = kc * 16 * BT_STRIDE;
            #pragma unroll
            for (int ntp = 0; ntp < 4; ntp++) {
                uint32_t bh0, bh1, bh2, bh3, bl0, bl1, bl2, bl3;
                ldsm4t(bh0, bh1, bh2, bh3, b_base + bko + ntp * 32);
                ldsm4t(bl0, bl1, bl2, bl3, b_base + (WH_BL - WH_BH) + bko + ntp * 32);
                mma16816(acc[2 * ntp],     ah0, ah1, ah2, ah3, bh0, bh1);
                mma16816(acc[2 * ntp],     ah0, ah1, ah2, ah3, bl0, bl1);
                mma16816(acc[2 * ntp],     al0, al1, al2, al3, bh0, bh1);
                mma16816(acc[2 * ntp + 1], ah0, ah1, ah2, ah3, bh2, bh3);
                mma16816(acc[2 * ntp + 1], ah0, ah1, ah2, ah3, bl2, bl3);
                mma16816(acc[2 * ntp + 1], al0, al1, al2, al3, bh2, bh3);
            }
        }
    }

    // ---- epilogue: bf16 hi/lo store + s_i/s_j partials ----
    const int r0 = wg_row * 16 + (lane >> 2);
    const int r1 = r0 + 8;
    const float* aish = (const float*)(sm + WH_AIJ);
    const float* ajsh = (const float*)(sm + WH_AIJ) + 128;

    float si0 = 0.f, si1 = 0.f, sj0 = 0.f, sj1 = 0.f;
    #pragma unroll
    for (int nt = 0; nt < 8; nt++) {
        const int cc = wg_col * 64 + nt * 8 + (lane & 3) * 2;
        uint32_t Hi0, Hi1;
        CVTPK(Hi0, acc[nt][0], acc[nt][1]);
        CVTPK(Hi1, acc[nt][2], acc[nt][3]);
        float u0 = acc[nt][0] - loF(Hi0), u1 = acc[nt][1] - hiF(Hi0);
        float u2 = acc[nt][2] - loF(Hi1), u3 = acc[nt][3] - hiF(Hi1);
        uint32_t Lo0, Lo1;
        CVTPK(Lo0, u0, u1); CVTPK(Lo1, u2, u3);
        *(uint32_t*)&d_Whbf_hi[(size_t)(row0 + r0) * FOUT + cc] = Hi0;
        *(uint32_t*)&d_Whbf_hi[(size_t)(row0 + r1) * FOUT + cc] = Hi1;
        *(uint32_t*)&d_Whbf_lo[(size_t)(row0 + r0) * FOUT + cc] = Lo0;
        *(uint32_t*)&d_Whbf_lo[(size_t)(row0 + r1) * FOUT + cc] = Lo1;
        float ai0 = aish[cc], ai1 = aish[cc + 1];
        float aj0 = ajsh[cc], aj1 = ajsh[cc + 1];
        si0 += acc[nt][0] * ai0 + acc[nt][1] * ai1;
        sj0 += acc[nt][0] * aj0 + acc[nt][1] * aj1;
        si1 += acc[nt][2] * ai0 + acc[nt][3] * ai1;
        sj1 += acc[nt][2] * aj0 + acc[nt][3] * aj1;
    }
    #pragma unroll
    for (int m = 1; m <= 2; m <<= 1) {
        si0 += __shfl_xor_sync(0xffffffffu, si0, m);
        sj0 += __shfl_xor_sync(0xffffffffu, sj0, m);
        si1 += __shfl_xor_sync(0xffffffffu, si1, m);
        sj1 += __shfl_xor_sync(0xffffffffu, sj1, m);
    }
    if ((lane & 3) == 0) {
        float* psi = (float*)(sm + WH_PSI) + wg_col * 64;
        float* psj = (float*)(sm + WH_PSJ) + wg_col * 64;
        psi[r0] = si0; psi[r1] = si1;
        psj[r0] = sj0; psj[r1] = sj1;
    }
    __syncthreads();
    if (t < 64) {
        const float* psi = (const float*)(sm + WH_PSI);
        const float* psj = (const float*)(sm + WH_PSJ);
        float si = psi[t] + psi[64 + t];
        float sj = psj[t] + psj[64 + t];
        d_si[row0 + t] = si;
        d_sj[row0 + t] = sj;
        // block-local max of sj over warps 0-1
        float m = sj;
        #pragma unroll
        for (int s = 16; s > 0; s >>= 1)
            m = fmaxf(m, __shfl_xor_sync(0xffffffffu, m, s));
        if (lane == 0) ((float*)(sm + WH_WMX))[w] = m;
    }
    __syncthreads();
    if (t == 0) {
        float m = fmaxf(((float*)(sm + WH_WMX))[0], ((float*)(sm + WH_WMX))[1]);
        atomicMax(&d_smax_bits[b], fkey(m));
    }
}

// ============================================================================
// Kernel B: exp tables (smax already in d_smax_bits)
// p_ij = exp(lrelu(si+sj) - m_i) = max(E1_i F1_j, E2_i F2_j)
// ============================================================================
__global__ __launch_bounds__(256) void tables_kernel() {
    const int idx = blockIdx.x * 256 + threadIdx.x;
    if (idx >= ROWS_TOTAL) return;
    const int b = idx >> 11;
    const float sm_ = funkey(d_smax_bits[b]);
    const float si = d_si[idx];
    const float sj = d_sj[idx];
    const float tt = si + sm_;
    const float mm = fmaxf(tt, 0.01f * tt);
    d_E12[idx] = make_float2(__expf(tt - mm), __expf(0.01f * tt - mm));
    const float u = sj - sm_;
    d_F12[idx] = make_float2(__expf(u), __expf(0.01f * u));
}

// ============================================================================
// Kernel C: mma.sync fused  h' = softmax(...) @ Wh — double-buffered,
// 64-row i-tiles, grid 256 -> 2 CTAs/SM. 8 warps = 4 rowgrp x 2 colgrp.
// F12 read directly from gmem (L2-resident, warp-uniform addresses).
// ============================================================================
#define OFF_AH  0         // 2 x 9216  [64 i][64 j] hi
#define OFF_AL  18432     // 2 x 9216  lo
#define OFF_BH  36864     // 2 x 17408 [64 j][128 o] hi
#define OFF_BL  71680     // 2 x 17408 lo
#define OFF_Z   106496    // 256 f
#define OFF_RZ  107520    // 64 f
#define SM_TOTAL_ATTN 107776

__global__ __launch_bounds__(256, 2) void attn_mma_kernel(float* __restrict__ out) {
    extern __shared__ __align__(16) char sm[];
    const uint32_t sm32 = smem_to_u32(sm);
    const int t      = threadIdx.x;
    const int w      = t >> 5;
    const int lane   = t & 31;
    const int wg_row = w >> 1;
    const int wg_col = w & 1;
    const int row0   = blockIdx.x * 64;
    const int b      = row0 >> 11;
    const int i      = t & 63;      // P-gen row
    const int grp    = t >> 6;      // P-gen j-group (16 j each)

    const float2 e = d_E12[row0 + i];
    const float e1 = e.x, e2 = e.y;
    float zacc = 0.0f;
    const float2* gF = &d_F12[(size_t)b * N_];

    float acc[8][4];
    #pragma unroll
    for (int n = 0; n < 8; n++)
        #pragma unroll
        for (int q = 0; q < 4; q++) acc[n][q] = 0.0f;

    const uint32_t a_base = sm32 + OFF_AH + (wg_row * 16 + (lane & 15)) * AT_STRIDE
                            + ((lane >> 4) << 4);
    const uint32_t b_base = sm32 + OFF_BH + (lane & 15) * BT_STRIDE
                            + ((lane >> 4) << 4) + wg_col * 128;

    const __nv_bfloat16* gWhi = &d_Whbf_hi[(size_t)b * N_ * FOUT];
    const __nv_bfloat16* gWlo = &d_Whbf_lo[(size_t)b * N_ * FOUT];

#define STAGE_B(CH, S) do { \
        const int _j0 = (CH) * 64; \
        const uint32_t _bh = sm32 + OFF_BH + (S) * 17408; \
        const uint32_t _bl = sm32 + OFF_BL + (S) * 17408; \
        _Pragma("unroll") \
        for (int m = 0; m < 4; m++) { \
            int idx = t + m * 256; \
            int j = idx >> 4, cq = idx & 15; \
            uint32_t ds = (uint32_t)(j * BT_STRIDE + cq * 16); \
            cp16(_bh + ds, gWhi + (size_t)(_j0 + j) * FOUT + cq * 8); \
            cp16(_bl + ds, gWlo + (size_t)(_j0 + j) * FOUT + cq * 8); \
        } \
        CP_COMMIT(); \
    } while (0)

#define GEN_A(CH, S) do { \
        const int _j0 = (CH) * 64; \
        char* _ah = sm + OFF_AH + (S) * 9216; \
        char* _al = sm + OFF_AL + (S) * 9216; \
        _Pragma("unroll") \
        for (int q = 0; q < 2; q++) { \
            int jl = grp * 16 + q * 8; \
            const float4* fp = (const float4*)&gF[_j0 + jl]; \
            float4 fa = fp[0], fb = fp[1], fc = fp[2], fd = fp[3]; \
            float p0 = fmaxf(e1 * fa.x, e2 * fa.y); \
            float p1 = fmaxf(e1 * fa.z, e2 * fa.w); \
            float p2 = fmaxf(e1 * fb.x, e2 * fb.y); \
            float p3 = fmaxf(e1 * fb.z, e2 * fb.w); \
            float p4 = fmaxf(e1 * fc.x, e2 * fc.y); \
            float p5 = fmaxf(e1 * fc.z, e2 * fc.w); \
            float p6 = fmaxf(e1 * fd.x, e2 * fd.y); \
            float p7 = fmaxf(e1 * fd.z, e2 * fd.w); \
            zacc += ((p0 + p1) + (p2 + p3)) + ((p4 + p5) + (p6 + p7)); \
            uint32_t h01, h23, h45, h67; \
            CVTPK(h01, p0, p1); CVTPK(h23, p2, p3); \
            CVTPK(h45, p4, p5); CVTPK(h67, p6, p7); \
            float r0_ = p0 - loF(h01), r1_ = p1 - hiF(h01); \
            float r2_ = p2 - loF(h23), r3_ = p3 - hiF(h23); \
            float r4_ = p4 - loF(h45), r5_ = p5 - hiF(h45); \
            float r6_ = p6 - loF(h67), r7_ = p7 - hiF(h67); \
            uint32_t l01, l23, l45, l67; \
            CVTPK(l01, r0_, r1_); CVTPK(l23, r2_, r3_); \
            CVTPK(l45, r4_, r5_); CVTPK(l67, r6_, r7_); \
            uint32_t off = (uint32_t)(i * AT_STRIDE + jl * 2); \
            *(uint4*)(_ah + off) = make_uint4(h01, h23, h45, h67); \
            *(uint4*)(_al + off) = make_uint4(l01, l23, l45, l67); \
        } \
    } while (0)

    STAGE_B(0, 0);
    GEN_A(0, 0);

    #pragma unroll 1
    for (int c = 0; c < 32; c++) {
        const int s = c & 1;
        CP_WAIT0();          // B(c) arrived (B(c+1) not yet issued)
        __syncthreads();     // compute(c-1) done; A(c)/B(c) visible
        if (c + 1 < 32) {
            STAGE_B(c + 1, s ^ 1);   // overlaps compute(c)
            GEN_A(c + 1, s ^ 1);
        }

        const uint32_t ah_b = a_base + s * 9216;
        const uint32_t al_b = ah_b + (OFF_AL - OFF_AH);
        const uint32_t bh_b = b_base + s * 17408;
        const uint32_t bl_b = bh_b + (OFF_BL - OFF_BH);
        #pragma unroll
        for (int kc = 0; kc < 4; kc++) {
            uint32_t ah0, ah1, ah2, ah3, al0, al1, al2, al3;
            ldsm4(ah0, ah1, ah2, ah3, ah_b + kc * 32);
            ldsm4(al0, al1, al2, al3, al_b + kc * 32);
            const uint32_t bko = kc * 16 * BT_STRIDE;
            #pragma unroll
            for (int ntp = 0; ntp < 4; ntp++) {
                uint32_t bh0, bh1, bh2, bh3, bl0, bl1, bl2, bl3;
                ldsm4t(bh0, bh1, bh2, bh3, bh_b + bko + ntp * 32);
                ldsm4t(bl0, bl1, bl2, bl3, bl_b + bko + ntp * 32);
                mma16816(acc[2 * ntp],     ah0, ah1, ah2, ah3, bh0, bh1);
                mma16816(acc[2 * ntp],     ah0, ah1, ah2, ah3, bl0, bl1);
                mma16816(acc[2 * ntp],     al0, al1, al2, al3, bh0, bh1);
                mma16816(acc[2 * ntp + 1], ah0, ah1, ah2, ah3, bh2, bh3);
                mma16816(acc[2 * ntp + 1], ah0, ah1, ah2, ah3, bl2, bl3);
                mma16816(acc[2 * ntp + 1], al0, al1, al2, al3, bh2, bh3);
            }
        }
    }

    // ---- Z reduction (4 j-group partials per row) ----
    ((float*)(sm + OFF_Z))[t] = zacc;
    __syncthreads();
    if (t < 64) {
        const float* z = (const float*)(sm + OFF_Z);
        float Z = (z[t] + z[64 + t]) + (z[128 + t] + z[192 + t]);
        ((float*)(sm + OFF_RZ))[t] = 1.0f / Z;
    }
    __syncthreads();

    // ---- epilogue: normalize + store ----
    {
        const int r0 = wg_row * 16 + (lane >> 2);
        const int r1 = r0 + 8;
        const float rz0 = ((float*)(sm + OFF_RZ))[r0];
        const float rz1 = ((float*)(sm + OFF_RZ))[r1];
        float* o0 = &out[(size_t)(row0 + r0) * FOUT];
        float* o1 = &out[(size_t)(row0 + r1) * FOUT];
        #pragma unroll
        for (int nt = 0; nt < 8; nt++) {
            const int cc = wg_col * 64 + nt * 8 + (lane & 3) * 2;
            *(float2*)&o0[cc] = make_float2(acc[nt][0] * rz0, acc[nt][1] * rz0);
            *(float2*)&o1[cc] = make_float2(acc[nt][2] * rz1, acc[nt][3] * rz1);
        }
    }
#undef STAGE_B
#undef GEN_A
}

// ============================================================================
// launch
// ============================================================================
extern "C" void kernel_launch(void* const* d_in, const int* in_sizes, int n_in,
                              void* d_out, int out_size) {
    const float* h    = (const float*)d_in[0];  // [8,2048,256]
    const float* W_fc = (const float*)d_in[1];  // [256,128]
    const float* a_i  = (const float*)d_in[2];  // [128]
    const float* a_j  = (const float*)d_in[3];  // [128]
    float* out = (float*)d_out;                 // [8,2048,128]

    cudaFuncSetAttribute(wh_mma_kernel,
                         cudaFuncAttributeMaxDynamicSharedMemorySize, SM_TOTAL_WH);
    cudaFuncSetAttribute(attn_mma_kernel,
                         cudaFuncAttributeMaxDynamicSharedMemorySize, SM_TOTAL_ATTN);

    wh_mma_kernel<<<ROWS_TOTAL / 64, 256, SM_TOTAL_WH>>>(h, W_fc, a_i, a_j);
    tables_kernel<<<ROWS_TOTAL / 256, 256>>>();
    attn_mma_kernel<<<ROWS_TOTAL / 64, 256, SM_TOTAL_ATTN>>>(out);
}